// round 16
// baseline (speedup 1.0000x reference)
#include <cuda_runtime.h>
#include <cuda_fp16.h>
#include <cstdint>

// ============================ problem constants ============================
#define HDIM 256
#define SDIM 512
#define BDIM 2048
#define CDIM 10
#define BT   16                 // batch columns per CTA (N)
#define NCTA (BDIM / BT)        // 128
#define NTHR 256                // 8 warps, each owns m=32 (two m16 tiles)

// ============================ SMEM layout (bytes) ==========================
// W_lo (ALL 16 kk): [8 warps][2 mtiles][16 kk][32 lanes][16B] = 131072
#define WLO_OFF 0
#define WLO_SZ  131072
// h tiles (fp16, single level): [k=256][n=16], 48B rows, 2 parities
#define HROW    48
#define HTILE   (HDIM * HROW)            // 12288
#define HB_OFF  WLO_SZ                   // 131072
#define HB_SZ   (2 * HTILE)              // 24576
// x staged [n=16][t=512] fp32, row pad 516 floats
#define XROW    516
#define XS_OFF  (HB_OFF + HB_SZ)         // 155648
#define XS_SZ   (BT * XROW * 4)          // 33024
#define SMEM_SZ (XS_OFF + XS_SZ)         // 188672

#define W_LO_SCALE 2048.0f
#define C_LO       (1.0f / 2048.0f)

// ============================ device helpers ===============================
__device__ __forceinline__ uint32_t smem_u32(const void* p) {
    return (uint32_t)__cvta_generic_to_shared(p);
}

__device__ __forceinline__ void ldsm_x4_t(uint32_t* r, uint32_t addr) {
    asm volatile("ldmatrix.sync.aligned.m8n8.x4.trans.shared.b16 "
                 "{%0,%1,%2,%3}, [%4];"
                 : "=r"(r[0]), "=r"(r[1]), "=r"(r[2]), "=r"(r[3])
                 : "r"(addr));
}

// fp16 MMA, fp32 accumulate
__device__ __forceinline__ void mma16816(float* d, const uint32_t* a,
                                         uint32_t b0, uint32_t b1) {
    asm volatile("mma.sync.aligned.m16n8k16.row.col.f32.f16.f16.f32 "
                 "{%0,%1,%2,%3},{%4,%5,%6,%7},{%8,%9},{%0,%1,%2,%3};"
                 : "+f"(d[0]), "+f"(d[1]), "+f"(d[2]), "+f"(d[3])
                 : "r"(a[0]), "r"(a[1]), "r"(a[2]), "r"(a[3]),
                   "r"(b0), "r"(b1));
}

// pack two fp32 -> fp16x2 (x in LOW half)
__device__ __forceinline__ uint32_t pack_h2(float x, float y) {
    uint32_t r;
    asm("cvt.rn.f16x2.f32 %0, %1, %2;" : "=r"(r) : "f"(y), "f"(x));
    return r;
}

// split W pair: fp16 hi pair (returned) + fp16 residual pair scaled by 2^11
__device__ __forceinline__ uint32_t splitW(float x, float y, uint32_t& lo) {
    uint32_t hi = pack_h2(x, y);
    __half2 hh = *reinterpret_cast<__half2*>(&hi);
    float fx = __half2float(__low2half(hh));
    float fy = __half2float(__high2half(hh));
    lo = pack_h2((x - fx) * W_LO_SCALE, (y - fy) * W_LO_SCALE);
    return hi;
}

// quad tanh: one rcp per four values (r12-validated)
__device__ __forceinline__ void tanh4(float* v) {
    const float C = 2.8853900817779268f;     // 2*log2(e)
    float u0 = fminf(v[0], 10.0f) * C;
    float u1 = fminf(v[1], 10.0f) * C;
    float u2 = fminf(v[2], 10.0f) * C;
    float u3 = fminf(v[3], 10.0f) * C;
    float d0 = exp2f(u0) + 1.0f;
    float d1 = exp2f(u1) + 1.0f;
    float d2 = exp2f(u2) + 1.0f;
    float d3 = exp2f(u3) + 1.0f;
    float m01 = d0 * d1, m23 = d2 * d3;
    float r;
    asm("rcp.approx.f32 %0, %1;" : "=f"(r) : "f"(m01 * m23));
    float r01 = r * m23, r23 = r * m01;
    v[0] = fmaf(r01 * d1, -2.0f, 1.0f);
    v[1] = fmaf(r01 * d0, -2.0f, 1.0f);
    v[2] = fmaf(r23 * d3, -2.0f, 1.0f);
    v[3] = fmaf(r23 * d2, -2.0f, 1.0f);
}

// ============================ kernel =======================================
extern "C" __global__ void __launch_bounds__(NTHR, 1)
rnn_fp16c_kernel(const float* __restrict__ x,
                 const float* __restrict__ W_hx,
                 const float* __restrict__ W_hh,
                 const float* __restrict__ W_ph,
                 const float* __restrict__ b_h,
                 const float* __restrict__ b_p,
                 float* __restrict__ out)
{
    extern __shared__ char sm[];
    const uint32_t smu = smem_u32(sm);

    const int tid  = threadIdx.x;
    const int w    = tid >> 5;          // warp id, owns rows 32w..32w+31
    const int lane = tid & 31;
    const int g    = lane >> 2;
    const int tIG  = lane & 3;
    const int m0   = w * 32;
    const int c0   = blockIdx.x * BT;

    // ---- stage x ----
    {
        float* xsw = (float*)(sm + XS_OFF);
        #pragma unroll 1
        for (int idx = tid; idx < BT * SDIM / 4; idx += NTHR) {
            int n = idx >> 7, t4 = idx & 127;
            float4 v = *reinterpret_cast<const float4*>(
                x + (size_t)(c0 + n) * SDIM + t4 * 4);
            *reinterpret_cast<float4*>(xsw + n * XROW + t4 * 4) = v;
        }
    }
    // ---- zero h parity-0 tile (h(0) = 0) ----
    {
        uint4 z = {0u, 0u, 0u, 0u};
        #pragma unroll 1
        for (int idx = tid; idx < HTILE / 16; idx += NTHR)
            *reinterpret_cast<uint4*>(sm + HB_OFF + idx * 16) = z;
    }

    // ---- gather W fragments: hi fp16 -> regs; lo (all 16 kk) -> SMEM ----
    uint32_t whi[128];                   // [mtile][kk][4]
    {
        #pragma unroll
        for (int tl = 0; tl < 2; ++tl) {
            const int rA = m0 + tl * 16 + g;
            const int rB = rA + 8;
            const float* Wr0 = W_hh + (size_t)rA * HDIM;
            const float* Wr1 = W_hh + (size_t)rB * HDIM;
            char* wlo_base = sm + WLO_OFF +
                ((size_t)(w * 2 + tl) * 16) * 512 + (size_t)lane * 16;
            #pragma unroll
            for (int kk = 0; kk < 16; ++kk) {
                int cl = kk * 16 + 2 * tIG;
                int ch = cl + 8;
                float2 w00 = *reinterpret_cast<const float2*>(Wr0 + cl);
                float2 w10 = *reinterpret_cast<const float2*>(Wr1 + cl);
                float2 w01 = *reinterpret_cast<const float2*>(Wr0 + ch);
                float2 w11 = *reinterpret_cast<const float2*>(Wr1 + ch);
                uint4 lo;
                whi[tl * 64 + kk * 4 + 0] = splitW(w00.x, w00.y, lo.x);
                whi[tl * 64 + kk * 4 + 1] = splitW(w10.x, w10.y, lo.y);
                whi[tl * 64 + kk * 4 + 2] = splitW(w01.x, w01.y, lo.z);
                whi[tl * 64 + kk * 4 + 3] = splitW(w11.x, w11.y, lo.w);
                *reinterpret_cast<uint4*>(wlo_base + (size_t)kk * 512) = lo;
            }
        }
    }

    // epilogue constants
    const int rA0 = m0 + g, rA1 = rA0 + 8, rB0 = rA0 + 16, rB1 = rA0 + 24;
    const float wxA0 = W_hx[rA0], wxA1 = W_hx[rA1];
    const float wxB0 = W_hx[rB0], wxB1 = W_hx[rB1];
    const float bhA0 = b_h[rA0],  bhA1 = b_h[rA1];
    const float bhB0 = b_h[rB0],  bhB1 = b_h[rB1];

    const uint32_t lm_off = (uint32_t)((((lane >> 3) & 1) * 8 + (lane & 7)) * HROW
                                       + ((lane >> 4) * 16));
    const uint32_t hb_u32 = smu + HB_OFF;
    const char* wloSA = sm + WLO_OFF + ((size_t)(w * 2) * 16) * 512 + (size_t)lane * 16;
    const char* wloSB = wloSA + 16 * 512;
    const float* xs = (const float*)(sm + XS_OFF);
    const int cc = 2 * tIG;

    __syncthreads();

    // ======================= time loop =======================
    #pragma unroll 1
    for (int t = 0; t < SDIM; ++t) {
        const int p = t & 1;
        const uint32_t hhi = hb_u32 + (uint32_t)(p * HTILE) + lm_off;

        const float x00 = xs[(cc + 0) * XROW + t];
        const float x01 = xs[(cc + 1) * XROW + t];
        const float x08 = xs[(cc + 8) * XROW + t];
        const float x09 = xs[(cc + 9) * XROW + t];

        // -------- 3-deep rotating buffers: prefetch distance 2 --------
        uint32_t bhv[3][4];
        uint4 wa[3], wb[3];
        ldsm_x4_t(bhv[0], hhi);
        wa[0] = *reinterpret_cast<const uint4*>(wloSA);
        wb[0] = *reinterpret_cast<const uint4*>(wloSB);
        ldsm_x4_t(bhv[1], hhi + (uint32_t)(16 * HROW));
        wa[1] = *reinterpret_cast<const uint4*>(wloSA + 512);
        wb[1] = *reinterpret_cast<const uint4*>(wloSB + 512);

        // main accumulators seeded with W_hx*x_t + b_h; lo accumulators zero
        float DA0[4] = { fmaf(wxA0, x00, bhA0), fmaf(wxA0, x01, bhA0),
                         fmaf(wxA1, x00, bhA1), fmaf(wxA1, x01, bhA1) };
        float DA1[4] = { fmaf(wxA0, x08, bhA0), fmaf(wxA0, x09, bhA0),
                         fmaf(wxA1, x08, bhA1), fmaf(wxA1, x09, bhA1) };
        float DB0[4] = { fmaf(wxB0, x00, bhB0), fmaf(wxB0, x01, bhB0),
                         fmaf(wxB1, x00, bhB1), fmaf(wxB1, x01, bhB1) };
        float DB1[4] = { fmaf(wxB0, x08, bhB0), fmaf(wxB0, x09, bhB0),
                         fmaf(wxB1, x08, bhB1), fmaf(wxB1, x09, bhB1) };
        float LA0[4] = {0.f,0.f,0.f,0.f};
        float LA1[4] = {0.f,0.f,0.f,0.f};
        float LB0[4] = {0.f,0.f,0.f,0.f};
        float LB1[4] = {0.f,0.f,0.f,0.f};

        #pragma unroll
        for (int kk = 0; kk < 16; ++kk) {
            const int cu = kk % 3;
            if (kk < 14) {
                const int nx = (kk + 2) % 3;
                ldsm_x4_t(bhv[nx], hhi + (uint32_t)(kk + 2) * (16 * HROW));
                wa[nx] = *reinterpret_cast<const uint4*>(wloSA + (kk + 2) * 512);
                wb[nx] = *reinterpret_cast<const uint4*>(wloSB + (kk + 2) * 512);
            }
            uint32_t wloA[4] = {wa[cu].x, wa[cu].y, wa[cu].z, wa[cu].w};
            uint32_t wloB[4] = {wb[cu].x, wb[cu].y, wb[cu].z, wb[cu].w};
            const uint32_t* aA  = whi + kk * 4;
            const uint32_t* aB  = whi + 64 + kk * 4;
            const uint32_t* bh4 = bhv[cu];

            mma16816(DA0, aA,   bh4[0], bh4[1]);
            mma16816(LA0, wloA, bh4[0], bh4[1]);
            mma16816(DA1, aA,   bh4[2], bh4[3]);
            mma16816(LA1, wloA, bh4[2], bh4[3]);
            mma16816(DB0, aB,   bh4[0], bh4[1]);
            mma16816(LB0, wloB, bh4[0], bh4[1]);
            mma16816(DB1, aB,   bh4[2], bh4[3]);
            mma16816(LB1, wloB, bh4[2], bh4[3]);
        }

        // ---- epilogue: combine lo, tanh4, pack fp16, STS (8 words) ----
        #pragma unroll
        for (int i = 0; i < 4; ++i) {
            DA0[i] = fmaf(C_LO, LA0[i], DA0[i]);
            DA1[i] = fmaf(C_LO, LA1[i], DA1[i]);
            DB0[i] = fmaf(C_LO, LB0[i], DB0[i]);
            DB1[i] = fmaf(C_LO, LB1[i], DB1[i]);
        }
        tanh4(DA0); tanh4(DA1); tanh4(DB0); tanh4(DB1);

        char* ohi = sm + HB_OFF + (p ^ 1) * HTILE;
        *reinterpret_cast<uint32_t*>(ohi + rA0 * HROW + 4 * tIG)      = pack_h2(DA0[0], DA0[1]);
        *reinterpret_cast<uint32_t*>(ohi + rA1 * HROW + 4 * tIG)      = pack_h2(DA0[2], DA0[3]);
        *reinterpret_cast<uint32_t*>(ohi + rA0 * HROW + 16 + 4 * tIG) = pack_h2(DA1[0], DA1[1]);
        *reinterpret_cast<uint32_t*>(ohi + rA1 * HROW + 16 + 4 * tIG) = pack_h2(DA1[2], DA1[3]);
        *reinterpret_cast<uint32_t*>(ohi + rB0 * HROW + 4 * tIG)      = pack_h2(DB0[0], DB0[1]);
        *reinterpret_cast<uint32_t*>(ohi + rB1 * HROW + 4 * tIG)      = pack_h2(DB0[2], DB0[3]);
        *reinterpret_cast<uint32_t*>(ohi + rB0 * HROW + 16 + 4 * tIG) = pack_h2(DB1[0], DB1[1]);
        *reinterpret_cast<uint32_t*>(ohi + rB1 * HROW + 16 + 4 * tIG) = pack_h2(DB1[2], DB1[3]);

        __syncthreads();
    }

    // ======================= final projection =======================
    // h(512) lives in parity-0 tile.
    if (tid < BT * CDIM) {
        const int b = tid / CDIM, c = tid % CDIM;
        const char* hb = sm + HB_OFF;
        float s = b_p[c];
        #pragma unroll 4
        for (int i = 0; i < HDIM; ++i) {
            float h = __half2float(*reinterpret_cast<const __half*>(
                          hb + i * HROW + 2 * b));
            s += W_ph[c * HDIM + i] * h;
        }
        out[(size_t)(c0 + b) * CDIM + c] = s;
    }
}

extern "C" void kernel_launch(void* const* d_in, const int* in_sizes, int n_in,
                              void* d_out, int out_size)
{
    const float* x    = (const float*)d_in[0];
    const float* W_hx = (const float*)d_in[1];
    const float* W_hh = (const float*)d_in[2];
    const float* W_ph = (const float*)d_in[3];
    const float* b_h  = (const float*)d_in[4];
    const float* b_p  = (const float*)d_in[5];
    float* out = (float*)d_out;

    cudaFuncSetAttribute(rnn_fp16c_kernel,
                         cudaFuncAttributeMaxDynamicSharedMemorySize, SMEM_SZ);
    rnn_fp16c_kernel<<<NCTA, NTHR, SMEM_SZ>>>(x, W_hx, W_hh, W_ph, b_h, b_p, out);
}

// round 17
// speedup vs baseline: 1.0370x; 1.0370x over previous
#include <cuda_runtime.h>
#include <cuda_fp16.h>
#include <cstdint>

// ============================ problem constants ============================
#define HDIM 256
#define SDIM 512
#define BDIM 2048
#define CDIM 10
#define BT   16                 // batch columns per CTA (N)
#define NCTA (BDIM / BT)        // 128
#define NTHR 256                // 8 warps, each owns m=32 (two m16 tiles)

// ============================ SMEM layout (bytes) ==========================
// W_lo (ALL 16 kk): [8 warps][2 mtiles][16 kk][32 lanes][16B] = 131072
#define WLO_OFF 0
#define WLO_SZ  131072
// h tiles (fp16, single level): [k=256][n=16], 48B rows, 2 parities
#define HROW    48
#define HTILE   (HDIM * HROW)            // 12288
#define HB_OFF  WLO_SZ                   // 131072
#define HB_SZ   (2 * HTILE)              // 24576
// x staged [n=16][t=512] fp32, row pad 516 floats
#define XROW    516
#define XS_OFF  (HB_OFF + HB_SZ)         // 155648
#define XS_SZ   (BT * XROW * 4)          // 33024
#define SMEM_SZ (XS_OFF + XS_SZ)         // 188672

// ============================ device helpers ===============================
__device__ __forceinline__ uint32_t smem_u32(const void* p) {
    return (uint32_t)__cvta_generic_to_shared(p);
}

__device__ __forceinline__ void ldsm_x4_t(uint32_t* r, uint32_t addr) {
    asm volatile("ldmatrix.sync.aligned.m8n8.x4.trans.shared.b16 "
                 "{%0,%1,%2,%3}, [%4];"
                 : "=r"(r[0]), "=r"(r[1]), "=r"(r[2]), "=r"(r[3])
                 : "r"(addr));
}

// fp16 MMA, fp32 accumulate
__device__ __forceinline__ void mma16816(float* d, const uint32_t* a,
                                         uint32_t b0, uint32_t b1) {
    asm volatile("mma.sync.aligned.m16n8k16.row.col.f32.f16.f16.f32 "
                 "{%0,%1,%2,%3},{%4,%5,%6,%7},{%8,%9},{%0,%1,%2,%3};"
                 : "+f"(d[0]), "+f"(d[1]), "+f"(d[2]), "+f"(d[3])
                 : "r"(a[0]), "r"(a[1]), "r"(a[2]), "r"(a[3]),
                   "r"(b0), "r"(b1));
}

// pack two fp32 -> fp16x2 (x in LOW half)
__device__ __forceinline__ uint32_t pack_h2(float x, float y) {
    uint32_t r;
    asm("cvt.rn.f16x2.f32 %0, %1, %2;" : "=r"(r) : "f"(y), "f"(x));
    return r;
}

// split W pair: fp16 hi pair (returned) + UNSCALED fp16 residual pair.
// Residuals (~2^-16) are fp16 subnormals; HMMA consumes denormal inputs,
// so both products can target the SAME fp32 accumulator.
__device__ __forceinline__ uint32_t splitW(float x, float y, uint32_t& lo) {
    uint32_t hi = pack_h2(x, y);
    __half2 hh = *reinterpret_cast<__half2*>(&hi);
    float fx = __half2float(__low2half(hh));
    float fy = __half2float(__high2half(hh));
    lo = pack_h2(x - fx, y - fy);
    return hi;
}

// quad tanh: one rcp per four values (r12-validated)
__device__ __forceinline__ void tanh4(float* v) {
    const float C = 2.8853900817779268f;     // 2*log2(e)
    float u0 = fminf(v[0], 10.0f) * C;
    float u1 = fminf(v[1], 10.0f) * C;
    float u2 = fminf(v[2], 10.0f) * C;
    float u3 = fminf(v[3], 10.0f) * C;
    float d0 = exp2f(u0) + 1.0f;
    float d1 = exp2f(u1) + 1.0f;
    float d2 = exp2f(u2) + 1.0f;
    float d3 = exp2f(u3) + 1.0f;
    float m01 = d0 * d1, m23 = d2 * d3;
    float r;
    asm("rcp.approx.f32 %0, %1;" : "=f"(r) : "f"(m01 * m23));
    float r01 = r * m23, r23 = r * m01;
    v[0] = fmaf(r01 * d1, -2.0f, 1.0f);
    v[1] = fmaf(r01 * d0, -2.0f, 1.0f);
    v[2] = fmaf(r23 * d3, -2.0f, 1.0f);
    v[3] = fmaf(r23 * d2, -2.0f, 1.0f);
}

// ============================ kernel =======================================
extern "C" __global__ void __launch_bounds__(NTHR, 1)
rnn_fp16d_kernel(const float* __restrict__ x,
                 const float* __restrict__ W_hx,
                 const float* __restrict__ W_hh,
                 const float* __restrict__ W_ph,
                 const float* __restrict__ b_h,
                 const float* __restrict__ b_p,
                 float* __restrict__ out)
{
    extern __shared__ char sm[];
    const uint32_t smu = smem_u32(sm);

    const int tid  = threadIdx.x;
    const int w    = tid >> 5;          // warp id, owns rows 32w..32w+31
    const int lane = tid & 31;
    const int g    = lane >> 2;
    const int tIG  = lane & 3;
    const int m0   = w * 32;
    const int c0   = blockIdx.x * BT;

    // ---- stage x ----
    {
        float* xsw = (float*)(sm + XS_OFF);
        #pragma unroll 1
        for (int idx = tid; idx < BT * SDIM / 4; idx += NTHR) {
            int n = idx >> 7, t4 = idx & 127;
            float4 v = *reinterpret_cast<const float4*>(
                x + (size_t)(c0 + n) * SDIM + t4 * 4);
            *reinterpret_cast<float4*>(xsw + n * XROW + t4 * 4) = v;
        }
    }
    // ---- zero h parity-0 tile (h(0) = 0) ----
    {
        uint4 z = {0u, 0u, 0u, 0u};
        #pragma unroll 1
        for (int idx = tid; idx < HTILE / 16; idx += NTHR)
            *reinterpret_cast<uint4*>(sm + HB_OFF + idx * 16) = z;
    }

    // ---- gather W fragments: hi fp16 -> regs; lo (all 16 kk) -> SMEM ----
    uint32_t whi[128];                   // [mtile][kk][4]
    {
        #pragma unroll
        for (int tl = 0; tl < 2; ++tl) {
            const int rA = m0 + tl * 16 + g;
            const int rB = rA + 8;
            const float* Wr0 = W_hh + (size_t)rA * HDIM;
            const float* Wr1 = W_hh + (size_t)rB * HDIM;
            char* wlo_base = sm + WLO_OFF +
                ((size_t)(w * 2 + tl) * 16) * 512 + (size_t)lane * 16;
            #pragma unroll
            for (int kk = 0; kk < 16; ++kk) {
                int cl = kk * 16 + 2 * tIG;
                int ch = cl + 8;
                float2 w00 = *reinterpret_cast<const float2*>(Wr0 + cl);
                float2 w10 = *reinterpret_cast<const float2*>(Wr1 + cl);
                float2 w01 = *reinterpret_cast<const float2*>(Wr0 + ch);
                float2 w11 = *reinterpret_cast<const float2*>(Wr1 + ch);
                uint4 lo;
                whi[tl * 64 + kk * 4 + 0] = splitW(w00.x, w00.y, lo.x);
                whi[tl * 64 + kk * 4 + 1] = splitW(w10.x, w10.y, lo.y);
                whi[tl * 64 + kk * 4 + 2] = splitW(w01.x, w01.y, lo.z);
                whi[tl * 64 + kk * 4 + 3] = splitW(w11.x, w11.y, lo.w);
                *reinterpret_cast<uint4*>(wlo_base + (size_t)kk * 512) = lo;
            }
        }
    }

    // epilogue constants
    const int rA0 = m0 + g, rA1 = rA0 + 8, rB0 = rA0 + 16, rB1 = rA0 + 24;
    const float wxA0 = W_hx[rA0], wxA1 = W_hx[rA1];
    const float wxB0 = W_hx[rB0], wxB1 = W_hx[rB1];
    const float bhA0 = b_h[rA0],  bhA1 = b_h[rA1];
    const float bhB0 = b_h[rB0],  bhB1 = b_h[rB1];

    const uint32_t lm_off = (uint32_t)((((lane >> 3) & 1) * 8 + (lane & 7)) * HROW
                                       + ((lane >> 4) * 16));
    const uint32_t hb_u32 = smu + HB_OFF;
    const char* wloSA = sm + WLO_OFF + ((size_t)(w * 2) * 16) * 512 + (size_t)lane * 16;
    const char* wloSB = wloSA + 16 * 512;
    const float* xs = (const float*)(sm + XS_OFF);
    const int cc = 2 * tIG;

    __syncthreads();

    // ======================= time loop =======================
    #pragma unroll 1
    for (int t = 0; t < SDIM; ++t) {
        const int p = t & 1;
        const uint32_t hhi = hb_u32 + (uint32_t)(p * HTILE) + lm_off;

        const float x00 = xs[(cc + 0) * XROW + t];
        const float x01 = xs[(cc + 1) * XROW + t];
        const float x08 = xs[(cc + 8) * XROW + t];
        const float x09 = xs[(cc + 9) * XROW + t];

        uint32_t bhv[2][4];
        uint4 wa[2], wb[2];
        ldsm_x4_t(bhv[0], hhi);
        wa[0] = *reinterpret_cast<const uint4*>(wloSA);
        wb[0] = *reinterpret_cast<const uint4*>(wloSB);

        // single accumulator set, seeded with W_hx*x_t + b_h
        float DA0[4] = { fmaf(wxA0, x00, bhA0), fmaf(wxA0, x01, bhA0),
                         fmaf(wxA1, x00, bhA1), fmaf(wxA1, x01, bhA1) };
        float DA1[4] = { fmaf(wxA0, x08, bhA0), fmaf(wxA0, x09, bhA0),
                         fmaf(wxA1, x08, bhA1), fmaf(wxA1, x09, bhA1) };
        float DB0[4] = { fmaf(wxB0, x00, bhB0), fmaf(wxB0, x01, bhB0),
                         fmaf(wxB1, x00, bhB1), fmaf(wxB1, x01, bhB1) };
        float DB1[4] = { fmaf(wxB0, x08, bhB0), fmaf(wxB0, x09, bhB0),
                         fmaf(wxB1, x08, bhB1), fmaf(wxB1, x09, bhB1) };

        #pragma unroll
        for (int kk = 0; kk < 16; ++kk) {
            const int cu = kk & 1, nx = cu ^ 1;
            if (kk < 15) {
                ldsm_x4_t(bhv[nx], hhi + (uint32_t)(kk + 1) * (16 * HROW));
                wa[nx] = *reinterpret_cast<const uint4*>(wloSA + (kk + 1) * 512);
                wb[nx] = *reinterpret_cast<const uint4*>(wloSB + (kk + 1) * 512);
            }
            uint32_t wloA[4] = {wa[cu].x, wa[cu].y, wa[cu].z, wa[cu].w};
            uint32_t wloB[4] = {wb[cu].x, wb[cu].y, wb[cu].z, wb[cu].w};
            const uint32_t* aA  = whi + kk * 4;
            const uint32_t* aB  = whi + 64 + kk * 4;
            const uint32_t* bh4 = bhv[cu];

            mma16816(DA0, aA,   bh4[0], bh4[1]);
            mma16816(DA0, wloA, bh4[0], bh4[1]);
            mma16816(DA1, aA,   bh4[2], bh4[3]);
            mma16816(DA1, wloA, bh4[2], bh4[3]);
            mma16816(DB0, aB,   bh4[0], bh4[1]);
            mma16816(DB0, wloB, bh4[0], bh4[1]);
            mma16816(DB1, aB,   bh4[2], bh4[3]);
            mma16816(DB1, wloB, bh4[2], bh4[3]);
        }

        // ---- epilogue: tanh4, pack fp16, STS (8 words) ----
        tanh4(DA0); tanh4(DA1); tanh4(DB0); tanh4(DB1);

        char* ohi = sm + HB_OFF + (p ^ 1) * HTILE;
        *reinterpret_cast<uint32_t*>(ohi + rA0 * HROW + 4 * tIG)      = pack_h2(DA0[0], DA0[1]);
        *reinterpret_cast<uint32_t*>(ohi + rA1 * HROW + 4 * tIG)      = pack_h2(DA0[2], DA0[3]);
        *reinterpret_cast<uint32_t*>(ohi + rA0 * HROW + 16 + 4 * tIG) = pack_h2(DA1[0], DA1[1]);
        *reinterpret_cast<uint32_t*>(ohi + rA1 * HROW + 16 + 4 * tIG) = pack_h2(DA1[2], DA1[3]);
        *reinterpret_cast<uint32_t*>(ohi + rB0 * HROW + 4 * tIG)      = pack_h2(DB0[0], DB0[1]);
        *reinterpret_cast<uint32_t*>(ohi + rB1 * HROW + 4 * tIG)      = pack_h2(DB0[2], DB0[3]);
        *reinterpret_cast<uint32_t*>(ohi + rB0 * HROW + 16 + 4 * tIG) = pack_h2(DB1[0], DB1[1]);
        *reinterpret_cast<uint32_t*>(ohi + rB1 * HROW + 16 + 4 * tIG) = pack_h2(DB1[2], DB1[3]);

        __syncthreads();
    }

    // ======================= final projection =======================
    // h(512) lives in parity-0 tile.
    if (tid < BT * CDIM) {
        const int b = tid / CDIM, c = tid % CDIM;
        const char* hb = sm + HB_OFF;
        float s = b_p[c];
        #pragma unroll 4
        for (int i = 0; i < HDIM; ++i) {
            float h = __half2float(*reinterpret_cast<const __half*>(
                          hb + i * HROW + 2 * b));
            s += W_ph[c * HDIM + i] * h;
        }
        out[(size_t)(c0 + b) * CDIM + c] = s;
    }
}

extern "C" void kernel_launch(void* const* d_in, const int* in_sizes, int n_in,
                              void* d_out, int out_size)
{
    const float* x    = (const float*)d_in[0];
    const float* W_hx = (const float*)d_in[1];
    const float* W_hh = (const float*)d_in[2];
    const float* W_ph = (const float*)d_in[3];
    const float* b_h  = (const float*)d_in[4];
    const float* b_p  = (const float*)d_in[5];
    float* out = (float*)d_out;

    cudaFuncSetAttribute(rnn_fp16d_kernel,
                         cudaFuncAttributeMaxDynamicSharedMemorySize, SMEM_SZ);
    rnn_fp16d_kernel<<<NCTA, NTHR, SMEM_SZ>>>(x, W_hx, W_hh, W_ph, b_h, b_p, out);
}